// round 1
// baseline (speedup 1.0000x reference)
#include <cuda_runtime.h>
#include <cuda_bf16.h>

// ---------------------------------------------------------------------------
// RBF network:  out[n] = sum_c w_c * exp(-beta_c * d2(n,c)) / sum_c exp(-beta_c * d2(n,c))
// d2 = |x|^2 + |c|^2 - 2 x.c
// Rewritten in log2 domain:
//   E(n,c) = bb_c*|x_n|^2 + a0_c*x0 + a1_c*x1 + a2_c*x2 + a3_c ,  r = 2^E
// with a_i = 2*beta*log2e*c_i, a3 = -beta*log2e*|c|^2, bb = -beta*log2e.
// Per (n,c): 4 FMA (packed f32x2 -> 2 per pair of points) + 1 MUFU EX2
// + packed accumulate. MUFU-bound by design.
// ---------------------------------------------------------------------------

#define LOG2E 1.4426950408889634f
#define NCENTER_MAX 2048
#define TPB 128
#define CPT 4   // points per thread (two f32x2 pairs)

static __device__ float4 g_cA[NCENTER_MAX];   // a0,a1,a2,a3
static __device__ float2 g_cB[NCENTER_MAX];   // bb, w

typedef unsigned long long u64;

__device__ __forceinline__ u64 pk2(float lo, float hi) {
    u64 r; asm("mov.b64 %0, {%1, %2};" : "=l"(r) : "f"(lo), "f"(hi)); return r;
}
__device__ __forceinline__ void upk2(u64 v, float &lo, float &hi) {
    asm("mov.b64 {%0, %1}, %2;" : "=f"(lo), "=f"(hi) : "l"(v));
}
__device__ __forceinline__ u64 fma2(u64 a, u64 b, u64 c) {
    u64 d; asm("fma.rn.f32x2 %0, %1, %2, %3;" : "=l"(d) : "l"(a), "l"(b), "l"(c)); return d;
}
__device__ __forceinline__ u64 add2(u64 a, u64 b) {
    u64 d; asm("add.rn.f32x2 %0, %1, %2;" : "=l"(d) : "l"(a), "l"(b)); return d;
}
__device__ __forceinline__ float ex2f(float x) {
    float r; asm("ex2.approx.ftz.f32 %0, %1;" : "=f"(r) : "f"(x)); return r;
}

__global__ void precompute_kernel(const float* __restrict__ centers,
                                  const float* __restrict__ beta,
                                  const float* __restrict__ lin_w, int C) {
    int c = blockIdx.x * blockDim.x + threadIdx.x;
    if (c >= C) return;
    float cx = centers[3*c+0], cy = centers[3*c+1], cz = centers[3*c+2];
    float bl = beta[c] * LOG2E;
    float4 A;
    A.x = 2.0f * bl * cx;
    A.y = 2.0f * bl * cy;
    A.z = 2.0f * bl * cz;
    A.w = -bl * (cx*cx + cy*cy + cz*cz);
    g_cA[c] = A;
    float2 B;
    B.x = -bl;
    B.y = lin_w[c];
    g_cB[c] = B;
}

__global__ __launch_bounds__(TPB)
void rbf_kernel(const float* __restrict__ x, float* __restrict__ out, int N, int C) {
    __shared__ float4 sA[2000];
    __shared__ float2 sB[2000];
    for (int i = threadIdx.x; i < C; i += TPB) { sA[i] = g_cA[i]; sB[i] = g_cB[i]; }
    __syncthreads();

    int base = (blockIdx.x * TPB + threadIdx.x) * CPT;
    if (base >= N) return;

    // 4 consecutive points = 12 consecutive floats, 16B aligned (base % 4 == 0)
    const float4* xv = reinterpret_cast<const float4*>(x + 3 * base);
    float4 v0 = xv[0], v1 = xv[1], v2 = xv[2];

    // pair A = points (0,1); pair B = points (2,3)
    u64 X0a = pk2(v0.x, v0.w), X1a = pk2(v0.y, v1.x), X2a = pk2(v0.z, v1.y);
    u64 X0b = pk2(v1.z, v2.y), X1b = pk2(v1.w, v2.z), X2b = pk2(v2.x, v2.w);

    float s0 = v0.x*v0.x + v0.y*v0.y + v0.z*v0.z;
    float s1 = v0.w*v0.w + v1.x*v1.x + v1.y*v1.y;
    float s2 = v1.z*v1.z + v1.w*v1.w + v2.x*v2.x;
    float s3 = v2.y*v2.y + v2.z*v2.z + v2.w*v2.w;
    u64 Sa = pk2(s0, s1), Sb = pk2(s2, s3);

    u64 suma = 0ull, dota = 0ull, sumb = 0ull, dotb = 0ull;  // bits 0 == (0.0f,0.0f)

    #pragma unroll 2
    for (int c = 0; c < C; ++c) {
        float4 A = sA[c];       // LDS.128
        float2 B = sB[c];       // LDS.64
        u64 A0 = pk2(A.x, A.x), A1 = pk2(A.y, A.y), A2 = pk2(A.z, A.z), A3 = pk2(A.w, A.w);
        u64 BB = pk2(B.x, B.x), W  = pk2(B.y, B.y);

        u64 ea = fma2(BB, Sa, fma2(A0, X0a, fma2(A1, X1a, fma2(A2, X2a, A3))));
        u64 eb = fma2(BB, Sb, fma2(A0, X0b, fma2(A1, X1b, fma2(A2, X2b, A3))));

        float e0, e1, e2, e3;
        upk2(ea, e0, e1); upk2(eb, e2, e3);
        u64 Ra = pk2(ex2f(e0), ex2f(e1));
        u64 Rb = pk2(ex2f(e2), ex2f(e3));

        suma = add2(suma, Ra); dota = fma2(W, Ra, dota);
        sumb = add2(sumb, Rb); dotb = fma2(W, Rb, dotb);
    }

    float su0, su1, su2, su3, d0, d1, d2, d3;
    upk2(suma, su0, su1); upk2(sumb, su2, su3);
    upk2(dota, d0, d1);   upk2(dotb, d2, d3);

    if (base + 0 < N) out[base + 0] = d0 / su0;
    if (base + 1 < N) out[base + 1] = d1 / su1;
    if (base + 2 < N) out[base + 2] = d2 / su2;
    if (base + 3 < N) out[base + 3] = d3 / su3;
}

extern "C" void kernel_launch(void* const* d_in, const int* in_sizes, int n_in,
                              void* d_out, int out_size) {
    const float* x       = (const float*)d_in[0];
    const float* centers = (const float*)d_in[1];
    const float* beta    = (const float*)d_in[2];
    const float* lin_w   = (const float*)d_in[3];
    float* out = (float*)d_out;

    int N = in_sizes[0] / 3;
    int C = in_sizes[2];

    precompute_kernel<<<(C + 255) / 256, 256>>>(centers, beta, lin_w, C);

    int nblocks = (N + TPB * CPT - 1) / (TPB * CPT);
    rbf_kernel<<<nblocks, TPB>>>(x, out, N, C);
}

// round 2
// speedup vs baseline: 2.1926x; 2.1926x over previous
#include <cuda_runtime.h>
#include <cuda_bf16.h>

// ---------------------------------------------------------------------------
// RBF network exploiting the dataset's separable structure:
//   centers = meshgrid(g1[20], g2[5], g3[20], indexing='ij').reshape(-1,3)
//   beta    = const (read beta[0] at runtime)
// Then exp(-beta*|x-c|^2) = u_i * v_j * w_k  with per-dim 1D Gaussians, and
//   out = ( sum_ijk W[i,j,k] u_i v_j w_k ) / ( (sum u)(sum v)(sum w) )
// Contraction k-first: 1 FMA per (point,center). 45 exps/point instead of 2000.
// Everything evaluated in packed f32x2 over pairs of points (2 pts / thread).
// Grid coords / beta / W are read from the input arrays at runtime.
// ---------------------------------------------------------------------------

#define LOG2E 1.4426950408889634f
#define NI 20
#define NJ 5
#define NK 20
#define NC (NI*NJ*NK)   // 2000
#define TPB 64

typedef unsigned long long u64;

__device__ __forceinline__ u64 pk2(float lo, float hi) {
    u64 r; asm("mov.b64 %0, {%1, %2};" : "=l"(r) : "f"(lo), "f"(hi)); return r;
}
__device__ __forceinline__ void upk2(u64 v, float &lo, float &hi) {
    asm("mov.b64 {%0, %1}, %2;" : "=f"(lo), "=f"(hi) : "l"(v));
}
__device__ __forceinline__ u64 fma2(u64 a, u64 b, u64 c) {
    u64 d; asm("fma.rn.f32x2 %0, %1, %2, %3;" : "=l"(d) : "l"(a), "l"(b), "l"(c)); return d;
}
__device__ __forceinline__ u64 add2(u64 a, u64 b) {
    u64 d; asm("add.rn.f32x2 %0, %1, %2;" : "=l"(d) : "l"(a), "l"(b)); return d;
}
__device__ __forceinline__ u64 mul2(u64 a, u64 b) {
    u64 d; asm("mul.rn.f32x2 %0, %1, %2;" : "=l"(d) : "l"(a), "l"(b)); return d;
}
__device__ __forceinline__ float ex2f(float x) {
    float r; asm("ex2.approx.ftz.f32 %0, %1;" : "=f"(r) : "f"(x)); return r;
}
// exp2 on both lanes of a packed pair
__device__ __forceinline__ u64 ex2p(u64 e) {
    float lo, hi; upk2(e, lo, hi);
    return pk2(ex2f(lo), ex2f(hi));
}

__global__ __launch_bounds__(TPB)
void rbf_sep_kernel(const float* __restrict__ x,
                    const float* __restrict__ centers,
                    const float* __restrict__ beta,
                    const float* __restrict__ lin_w,
                    float* __restrict__ out, int N) {
    // W duplicated into u64 pairs for direct use as f32x2 operands (16 KB),
    // plus negated grid coordinates duplicated the same way.
    __shared__ u64 sW2[NC];
    __shared__ u64 sng1[NI], sng2[NJ], sng3[NK];

    for (int c = threadIdx.x; c < NC; c += TPB) {
        float w = lin_w[c];
        sW2[c] = pk2(w, w);
    }
    if (threadIdx.x < NI) {
        float g = centers[3 * (threadIdx.x * (NJ * NK)) + 0];
        sng1[threadIdx.x] = pk2(-g, -g);
    }
    if (threadIdx.x < NJ) {
        float g = centers[3 * (threadIdx.x * NK) + 1];
        sng2[threadIdx.x] = pk2(-g, -g);
    }
    if (threadIdx.x < NK) {
        float g = centers[3 * threadIdx.x + 2];
        sng3[threadIdx.x] = pk2(-g, -g);
    }
    __syncthreads();

    int t = blockIdx.x * TPB + threadIdx.x;          // pair index
    int p0 = 2 * t;
    if (p0 + 1 >= N) return;                          // N is even for this dataset

    float nbl = -beta[0] * LOG2E;                     // -beta * log2(e)
    u64 NBL = pk2(nbl, nbl);

    // load 2 points (6 floats, 8B aligned)
    const float2* xv = reinterpret_cast<const float2*>(x + 6 * t);
    float2 f0 = xv[0], f1 = xv[1], f2 = xv[2];
    u64 X0 = pk2(f0.x, f1.y);
    u64 X1 = pk2(f0.y, f2.x);
    u64 X2 = pk2(f1.x, f2.y);

    // per-dim 1D Gaussians (packed over the 2 points)
    u64 wv[NK];
    u64 V[NJ];
    u64 sumw = 0ull, sumv = 0ull;

    #pragma unroll
    for (int k = 0; k < NK; ++k) {
        u64 d = add2(X2, sng3[k]);
        wv[k] = ex2p(mul2(mul2(d, d), NBL));
        sumw = add2(sumw, wv[k]);
    }
    #pragma unroll
    for (int j = 0; j < NJ; ++j) {
        u64 d = add2(X1, sng2[j]);
        V[j] = ex2p(mul2(mul2(d, d), NBL));
        sumv = add2(sumv, V[j]);
    }

    u64 num = 0ull, sumu = 0ull;

    for (int i = 0; i < NI; ++i) {
        // u_i inline
        u64 du = add2(X0, sng1[i]);
        u64 U = ex2p(mul2(mul2(du, du), NBL));
        sumu = add2(sumu, U);

        u64 tacc = 0ull;
        const ulonglong2* Wp = reinterpret_cast<const ulonglong2*>(&sW2[i * (NJ * NK)]);
        #pragma unroll
        for (int j = 0; j < NJ; ++j) {
            u64 r0 = 0ull, r1 = 0ull;
            #pragma unroll
            for (int kk = 0; kk < NK / 2; ++kk) {
                ulonglong2 wq = Wp[j * (NK / 2) + kk];   // LDS.128: 2 dup'd coeffs
                r0 = fma2(wq.x, wv[2 * kk + 0], r0);
                r1 = fma2(wq.y, wv[2 * kk + 1], r1);
            }
            tacc = fma2(V[j], add2(r0, r1), tacc);
        }
        num = fma2(U, tacc, num);
    }

    u64 den = mul2(mul2(sumu, sumv), sumw);
    float n0, n1, d0, d1;
    upk2(num, n0, n1);
    upk2(den, d0, d1);

    float2 o;
    o.x = __fdividef(n0, d0);
    o.y = __fdividef(n1, d1);
    *reinterpret_cast<float2*>(out + p0) = o;
}

extern "C" void kernel_launch(void* const* d_in, const int* in_sizes, int n_in,
                              void* d_out, int out_size) {
    const float* x       = (const float*)d_in[0];
    const float* centers = (const float*)d_in[1];
    const float* beta    = (const float*)d_in[2];
    const float* lin_w   = (const float*)d_in[3];
    float* out = (float*)d_out;

    int N = in_sizes[0] / 3;          // 131072
    int pairs = N / 2;                // 65536
    int nblocks = (pairs + TPB - 1) / TPB;   // 1024

    rbf_sep_kernel<<<nblocks, TPB>>>(x, centers, beta, lin_w, out, N);
}

// round 3
// speedup vs baseline: 2.3218x; 1.0589x over previous
#include <cuda_runtime.h>
#include <cuda_bf16.h>

// ---------------------------------------------------------------------------
// Separable RBF network (centers = 20x5x20 meshgrid, uniform beta):
//   exp(-beta|x-c|^2) = u_i(x0) * v_j(x1) * w_k(x2)
//   out = ( sum_ijk W[i,j,k] u_i v_j w_k ) / ( (sum u)(sum v)(sum w) )
// f32x2 lanes pack two ADJACENT k-indices of the SAME point, so the weight
// operand of the inner fma2 is a naturally-paired float2 straight from an
// LDS.128 of raw W — 4 fma2 per LDS.128, no duplicated smem, 8 KB.
// Each thread processes 2 points. Grid/beta/W all read from inputs at runtime.
// ---------------------------------------------------------------------------

#define LOG2E 1.4426950408889634f
#define NI 20
#define NJ 5
#define NK 20
#define NC (NI*NJ*NK)
#define TPB 128

typedef unsigned long long u64;

__device__ __forceinline__ u64 pk2(float lo, float hi) {
    u64 r; asm("mov.b64 %0, {%1, %2};" : "=l"(r) : "f"(lo), "f"(hi)); return r;
}
__device__ __forceinline__ void upk2(u64 v, float &lo, float &hi) {
    asm("mov.b64 {%0, %1}, %2;" : "=f"(lo), "=f"(hi) : "l"(v));
}
__device__ __forceinline__ u64 fma2(u64 a, u64 b, u64 c) {
    u64 d; asm("fma.rn.f32x2 %0, %1, %2, %3;" : "=l"(d) : "l"(a), "l"(b), "l"(c)); return d;
}
__device__ __forceinline__ u64 add2(u64 a, u64 b) {
    u64 d; asm("add.rn.f32x2 %0, %1, %2;" : "=l"(d) : "l"(a), "l"(b)); return d;
}
__device__ __forceinline__ float ex2f(float x) {
    float r; asm("ex2.approx.ftz.f32 %0, %1;" : "=f"(r) : "f"(x)); return r;
}

__global__ __launch_bounds__(TPB)
void rbf_sep_kernel(const float* __restrict__ x,
                    const float* __restrict__ centers,
                    const float* __restrict__ beta,
                    const float* __restrict__ lin_w,
                    float* __restrict__ out, int N) {
    __shared__ __align__(16) float sW[NC];          // raw weights, 8 KB
    __shared__ float sg1[NI], sg2[NJ], sg3[NK];

    for (int c = threadIdx.x; c < NC; c += TPB) sW[c] = lin_w[c];
    if (threadIdx.x < NI) sg1[threadIdx.x] = centers[3 * (threadIdx.x * (NJ * NK)) + 0];
    if (threadIdx.x < NJ) sg2[threadIdx.x] = centers[3 * (threadIdx.x * NK) + 1];
    if (threadIdx.x < NK) sg3[threadIdx.x] = centers[3 * threadIdx.x + 2];
    __syncthreads();

    int t = blockIdx.x * TPB + threadIdx.x;     // pair-of-points index
    int p0 = 2 * t;
    if (p0 + 1 >= N) return;

    float nbl = -beta[0] * LOG2E;               // -beta * log2(e)

    const float2* xv = reinterpret_cast<const float2*>(x + 6 * t);
    float2 f0 = xv[0], f1 = xv[1], f2 = xv[2];
    float xa0 = f0.x, xa1 = f0.y, xa2 = f1.x;   // point a
    float xb0 = f1.y, xb1 = f2.x, xb2 = f2.y;   // point b

    // k-dim Gaussians as (k, k+1) register pairs, per point
    u64 wva[NK / 2], wvb[NK / 2];
    float sumwa = 0.f, sumwb = 0.f;
    #pragma unroll
    for (int k = 0; k < NK; k += 2) {
        float g0 = sg3[k], g1v = sg3[k + 1];
        float da0 = xa2 - g0,  da1 = xa2 - g1v;
        float db0 = xb2 - g0,  db1 = xb2 - g1v;
        float ea0 = ex2f(nbl * da0 * da0), ea1 = ex2f(nbl * da1 * da1);
        float eb0 = ex2f(nbl * db0 * db0), eb1 = ex2f(nbl * db1 * db1);
        sumwa += ea0 + ea1;  sumwb += eb0 + eb1;
        wva[k / 2] = pk2(ea0, ea1);
        wvb[k / 2] = pk2(eb0, eb1);
    }

    // j-dim Gaussians, duplicated pairs per point
    u64 Va[NJ], Vb[NJ];
    float sumva = 0.f, sumvb = 0.f;
    #pragma unroll
    for (int j = 0; j < NJ; ++j) {
        float g = sg2[j];
        float da = xa1 - g, db = xb1 - g;
        float va = ex2f(nbl * da * da), vb = ex2f(nbl * db * db);
        sumva += va;  sumvb += vb;
        Va[j] = pk2(va, va);
        Vb[j] = pk2(vb, vb);
    }

    u64 numa = 0ull, numb = 0ull;
    float sumua = 0.f, sumub = 0.f;

    #pragma unroll 4
    for (int i = 0; i < NI; ++i) {
        float dua = xa0 - sg1[i], dub = xb0 - sg1[i];
        float ua = ex2f(nbl * dua * dua), ub = ex2f(nbl * dub * dub);
        sumua += ua;  sumub += ub;
        u64 Ua = pk2(ua, ua), Ub = pk2(ub, ub);

        u64 ta = 0ull, tb = 0ull;
        const float4* Wp = reinterpret_cast<const float4*>(&sW[i * (NJ * NK)]);
        #pragma unroll
        for (int j = 0; j < NJ; ++j) {
            u64 ka0 = 0ull, ka1 = 0ull, kb0 = 0ull, kb1 = 0ull;
            #pragma unroll
            for (int q = 0; q < NK / 4; ++q) {      // 5 x LDS.128, 4 coeffs each
                float4 w4 = Wp[j * (NK / 4) + q];
                u64 wlo = pk2(w4.x, w4.y);          // natural (W_k, W_{k+1}) pair
                u64 whi = pk2(w4.z, w4.w);
                ka0 = fma2(wlo, wva[2 * q + 0], ka0);
                ka1 = fma2(whi, wva[2 * q + 1], ka1);
                kb0 = fma2(wlo, wvb[2 * q + 0], kb0);
                kb1 = fma2(whi, wvb[2 * q + 1], kb1);
            }
            ta = fma2(Va[j], add2(ka0, ka1), ta);
            tb = fma2(Vb[j], add2(kb0, kb1), tb);
        }
        numa = fma2(Ua, ta, numa);
        numb = fma2(Ub, tb, numb);
    }

    float na0, na1, nb0, nb1;
    upk2(numa, na0, na1);
    upk2(numb, nb0, nb1);
    float num_a = na0 + na1;
    float num_b = nb0 + nb1;
    float den_a = sumua * sumva * sumwa;
    float den_b = sumub * sumvb * sumwb;

    float2 o;
    o.x = __fdividef(num_a, den_a);
    o.y = __fdividef(num_b, den_b);
    *reinterpret_cast<float2*>(out + p0) = o;
}

extern "C" void kernel_launch(void* const* d_in, const int* in_sizes, int n_in,
                              void* d_out, int out_size) {
    const float* x       = (const float*)d_in[0];
    const float* centers = (const float*)d_in[1];
    const float* beta    = (const float*)d_in[2];
    const float* lin_w   = (const float*)d_in[3];
    float* out = (float*)d_out;

    int N = in_sizes[0] / 3;               // 131072
    int pairs = N / 2;                     // 65536
    int nblocks = (pairs + TPB - 1) / TPB; // 512

    rbf_sep_kernel<<<nblocks, TPB>>>(x, centers, beta, lin_w, out, N);
}

// round 4
// speedup vs baseline: 3.8921x; 1.6763x over previous
#include <cuda_runtime.h>
#include <cuda_bf16.h>

// ---------------------------------------------------------------------------
// Separable RBF network (centers = 20x5x20 meshgrid, uniform beta):
//   exp(-beta|x-c|^2) = u_i(x0) * v_j(x1) * w_k(x2)
//   out = ( sum_ijk W[i,j,k] u_i v_j w_k ) / ( (sum u)(sum v)(sum w) )
// f32x2 lanes pack two ADJACENT k-indices of the SAME point; the weight
// operand of the inner fma2 comes naturally paired from an LDS.128 of raw W.
// FOUR points per thread: one LDS.128 feeds 8 independent fma2 chains,
// hiding both LDS latency and FMA RAW latency at low occupancy.
// Grid coords / beta / W are all read from the input arrays at runtime.
// ---------------------------------------------------------------------------

#define LOG2E 1.4426950408889634f
#define NI 20
#define NJ 5
#define NK 20
#define NC (NI*NJ*NK)
#define TPB 64
#define PPT 4   // points per thread

typedef unsigned long long u64;

__device__ __forceinline__ u64 pk2(float lo, float hi) {
    u64 r; asm("mov.b64 %0, {%1, %2};" : "=l"(r) : "f"(lo), "f"(hi)); return r;
}
__device__ __forceinline__ void upk2(u64 v, float &lo, float &hi) {
    asm("mov.b64 {%0, %1}, %2;" : "=f"(lo), "=f"(hi) : "l"(v));
}
__device__ __forceinline__ u64 fma2(u64 a, u64 b, u64 c) {
    u64 d; asm("fma.rn.f32x2 %0, %1, %2, %3;" : "=l"(d) : "l"(a), "l"(b), "l"(c)); return d;
}
__device__ __forceinline__ u64 add2(u64 a, u64 b) {
    u64 d; asm("add.rn.f32x2 %0, %1, %2;" : "=l"(d) : "l"(a), "l"(b)); return d;
}
__device__ __forceinline__ float ex2f(float x) {
    float r; asm("ex2.approx.ftz.f32 %0, %1;" : "=f"(r) : "f"(x)); return r;
}

__global__ __launch_bounds__(TPB)
void rbf_sep_kernel(const float* __restrict__ x,
                    const float* __restrict__ centers,
                    const float* __restrict__ beta,
                    const float* __restrict__ lin_w,
                    float* __restrict__ out, int N) {
    __shared__ __align__(16) float sW[NC];     // raw weights, 8 KB
    __shared__ float sg1[NI], sg2[NJ], sg3[NK];

    for (int c = threadIdx.x; c < NC; c += TPB) sW[c] = lin_w[c];
    if (threadIdx.x < NI) sg1[threadIdx.x] = centers[3 * (threadIdx.x * (NJ * NK)) + 0];
    if (threadIdx.x < NJ) sg2[threadIdx.x] = centers[3 * (threadIdx.x * NK) + 1];
    if (threadIdx.x < NK) sg3[threadIdx.x] = centers[3 * threadIdx.x + 2];
    __syncthreads();

    int t = blockIdx.x * TPB + threadIdx.x;    // group-of-4-points index
    int p0 = PPT * t;
    if (p0 + PPT - 1 >= N) return;             // N divisible by 4 for this dataset

    float nbl = -beta[0] * LOG2E;              // -beta * log2(e)

    // 4 points = 12 floats = 3 x float4, 16B aligned
    const float4* xv = reinterpret_cast<const float4*>(x + 3 * p0);
    float4 q0 = xv[0], q1 = xv[1], q2 = xv[2];
    float X0[PPT] = { q0.x, q0.w, q1.z, q2.y };
    float X1[PPT] = { q0.y, q1.x, q1.w, q2.z };
    float X2[PPT] = { q0.z, q1.y, q2.x, q2.w };

    // k-dim Gaussians as (k, k+1) register pairs, per point
    u64 wv[PPT][NK / 2];
    float sumw[PPT] = {0.f, 0.f, 0.f, 0.f};
    #pragma unroll
    for (int k = 0; k < NK; k += 2) {
        float g0 = sg3[k], g1 = sg3[k + 1];
        #pragma unroll
        for (int p = 0; p < PPT; ++p) {
            float d0 = X2[p] - g0, d1 = X2[p] - g1;
            float e0 = ex2f(nbl * d0 * d0), e1 = ex2f(nbl * d1 * d1);
            sumw[p] += e0 + e1;
            wv[p][k / 2] = pk2(e0, e1);
        }
    }

    // j-dim Gaussians, duplicated pairs per point
    u64 V[PPT][NJ];
    float sumv[PPT] = {0.f, 0.f, 0.f, 0.f};
    #pragma unroll
    for (int j = 0; j < NJ; ++j) {
        float g = sg2[j];
        #pragma unroll
        for (int p = 0; p < PPT; ++p) {
            float d = X1[p] - g;
            float v = ex2f(nbl * d * d);
            sumv[p] += v;
            V[p][j] = pk2(v, v);
        }
    }

    // fold sumv*sumw now; only sumu remains live through the main loop
    float svw[PPT];
    #pragma unroll
    for (int p = 0; p < PPT; ++p) svw[p] = sumv[p] * sumw[p];

    u64 num[PPT] = {0ull, 0ull, 0ull, 0ull};
    float sumu[PPT] = {0.f, 0.f, 0.f, 0.f};

    for (int i = 0; i < NI; ++i) {
        float gi = sg1[i];
        u64 U[PPT];
        #pragma unroll
        for (int p = 0; p < PPT; ++p) {
            float d = X0[p] - gi;
            float u = ex2f(nbl * d * d);
            sumu[p] += u;
            U[p] = pk2(u, u);
        }

        u64 ta[PPT] = {0ull, 0ull, 0ull, 0ull};
        const float4* Wp = reinterpret_cast<const float4*>(&sW[i * (NJ * NK)]);
        #pragma unroll
        for (int j = 0; j < NJ; ++j) {
            u64 k0[PPT] = {0ull, 0ull, 0ull, 0ull};
            u64 k1[PPT] = {0ull, 0ull, 0ull, 0ull};
            #pragma unroll
            for (int q = 0; q < NK / 4; ++q) {     // 5 x LDS.128, 4 coeffs each
                float4 w4 = Wp[j * (NK / 4) + q];
                u64 wlo = pk2(w4.x, w4.y);         // natural (W_k, W_{k+1}) pairs
                u64 whi = pk2(w4.z, w4.w);
                #pragma unroll
                for (int p = 0; p < PPT; ++p) {
                    k0[p] = fma2(wlo, wv[p][2 * q + 0], k0[p]);
                    k1[p] = fma2(whi, wv[p][2 * q + 1], k1[p]);
                }
            }
            #pragma unroll
            for (int p = 0; p < PPT; ++p)
                ta[p] = fma2(V[p][j], add2(k0[p], k1[p]), ta[p]);
        }
        #pragma unroll
        for (int p = 0; p < PPT; ++p)
            num[p] = fma2(U[p], ta[p], num[p]);
    }

    float4 o;
    float res[PPT];
    #pragma unroll
    for (int p = 0; p < PPT; ++p) {
        float nlo, nhi;
        upk2(num[p], nlo, nhi);
        res[p] = __fdividef(nlo + nhi, sumu[p] * svw[p]);
    }
    o.x = res[0]; o.y = res[1]; o.z = res[2]; o.w = res[3];
    *reinterpret_cast<float4*>(out + p0) = o;
}

extern "C" void kernel_launch(void* const* d_in, const int* in_sizes, int n_in,
                              void* d_out, int out_size) {
    const float* x       = (const float*)d_in[0];
    const float* centers = (const float*)d_in[1];
    const float* beta    = (const float*)d_in[2];
    const float* lin_w   = (const float*)d_in[3];
    float* out = (float*)d_out;

    int N = in_sizes[0] / 3;                          // 131072
    int groups = N / PPT;                             // 32768
    int nblocks = (groups + TPB - 1) / TPB;           // 512

    rbf_sep_kernel<<<nblocks, TPB>>>(x, centers, beta, lin_w, out, N);
}

// round 5
// speedup vs baseline: 3.9099x; 1.0046x over previous
#include <cuda_runtime.h>
#include <cuda_bf16.h>

// ---------------------------------------------------------------------------
// Separable RBF network (centers = 20x5x20 meshgrid, uniform beta):
//   exp(-beta|x-c|^2) = u_i(x0) * v_j(x1) * w_k(x2)
//   out = ( sum_ijk W[i,j,k] u_i v_j w_k ) / ( (sum u)(sum v)(sum w) )
// f32x2 lanes pack two adjacent k-indices of the same point; weights come
// naturally paired from LDS.128 of raw W. Four points per thread, and the
// outer i-loop (20 iters) is SPLIT across lane pairs (lane^1): each thread
// does 10 i-iters for the same 4 points; partial num/sumu merged by shfl.
// Doubles occupancy at constant ILP and register pressure.
// ---------------------------------------------------------------------------

#define LOG2E 1.4426950408889634f
#define NI 20
#define NJ 5
#define NK 20
#define NC (NI*NJ*NK)
#define TPB 64
#define PPT 4   // points per group (2 threads cooperate on one group)

typedef unsigned long long u64;

__device__ __forceinline__ u64 pk2(float lo, float hi) {
    u64 r; asm("mov.b64 %0, {%1, %2};" : "=l"(r) : "f"(lo), "f"(hi)); return r;
}
__device__ __forceinline__ void upk2(u64 v, float &lo, float &hi) {
    asm("mov.b64 {%0, %1}, %2;" : "=f"(lo), "=f"(hi) : "l"(v));
}
__device__ __forceinline__ u64 fma2(u64 a, u64 b, u64 c) {
    u64 d; asm("fma.rn.f32x2 %0, %1, %2, %3;" : "=l"(d) : "l"(a), "l"(b), "l"(c)); return d;
}
__device__ __forceinline__ u64 add2(u64 a, u64 b) {
    u64 d; asm("add.rn.f32x2 %0, %1, %2;" : "=l"(d) : "l"(a), "l"(b)); return d;
}
__device__ __forceinline__ float ex2f(float x) {
    float r; asm("ex2.approx.ftz.f32 %0, %1;" : "=f"(r) : "f"(x)); return r;
}

__global__ __launch_bounds__(TPB)
void rbf_sep_kernel(const float* __restrict__ x,
                    const float* __restrict__ centers,
                    const float* __restrict__ beta,
                    const float* __restrict__ lin_w,
                    float* __restrict__ out, int N) {
    __shared__ __align__(16) float sW[NC];     // raw weights, 8 KB
    __shared__ float sg1[NI], sg2[NJ], sg3[NK];

    for (int c = threadIdx.x; c < NC; c += TPB) sW[c] = lin_w[c];
    if (threadIdx.x < NI) sg1[threadIdx.x] = centers[3 * (threadIdx.x * (NJ * NK)) + 0];
    if (threadIdx.x < NJ) sg2[threadIdx.x] = centers[3 * (threadIdx.x * NK) + 1];
    if (threadIdx.x < NK) sg3[threadIdx.x] = centers[3 * threadIdx.x + 2];
    __syncthreads();

    int tid   = blockIdx.x * TPB + threadIdx.x;
    int group = tid >> 1;           // 4-point group index
    int half  = tid & 1;            // which half of the i-range this thread owns
    int p0 = PPT * group;
    if (p0 + PPT - 1 >= N) return;  // N divisible by 4 for this dataset

    float nbl = -beta[0] * LOG2E;   // -beta * log2(e)

    // 4 points = 12 floats = 3 x float4, 16B aligned
    const float4* xv = reinterpret_cast<const float4*>(x + 3 * p0);
    float4 q0 = xv[0], q1 = xv[1], q2 = xv[2];
    float X0[PPT] = { q0.x, q0.w, q1.z, q2.y };
    float X1[PPT] = { q0.y, q1.x, q1.w, q2.z };
    float X2[PPT] = { q0.z, q1.y, q2.x, q2.w };

    // k-dim Gaussians as (k, k+1) register pairs, per point (both threads of
    // a pair compute these redundantly — cheap, 45 exps)
    u64 wv[PPT][NK / 2];
    float sumw[PPT] = {0.f, 0.f, 0.f, 0.f};
    #pragma unroll
    for (int k = 0; k < NK; k += 2) {
        float g0 = sg3[k], g1 = sg3[k + 1];
        #pragma unroll
        for (int p = 0; p < PPT; ++p) {
            float d0 = X2[p] - g0, d1 = X2[p] - g1;
            float e0 = ex2f(nbl * d0 * d0), e1 = ex2f(nbl * d1 * d1);
            sumw[p] += e0 + e1;
            wv[p][k / 2] = pk2(e0, e1);
        }
    }

    // j-dim Gaussians, duplicated pairs per point
    u64 V[PPT][NJ];
    float sumv[PPT] = {0.f, 0.f, 0.f, 0.f};
    #pragma unroll
    for (int j = 0; j < NJ; ++j) {
        float g = sg2[j];
        #pragma unroll
        for (int p = 0; p < PPT; ++p) {
            float d = X1[p] - g;
            float v = ex2f(nbl * d * d);
            sumv[p] += v;
            V[p][j] = pk2(v, v);
        }
    }

    float svw[PPT];
    #pragma unroll
    for (int p = 0; p < PPT; ++p) svw[p] = sumv[p] * sumw[p];

    u64 num[PPT] = {0ull, 0ull, 0ull, 0ull};
    float sumu[PPT] = {0.f, 0.f, 0.f, 0.f};

    int ibeg = half * (NI / 2);     // this thread's half of the i-range
    #pragma unroll 2
    for (int ii = 0; ii < NI / 2; ++ii) {
        int i = ibeg + ii;
        float gi = sg1[i];
        u64 U[PPT];
        #pragma unroll
        for (int p = 0; p < PPT; ++p) {
            float d = X0[p] - gi;
            float u = ex2f(nbl * d * d);
            sumu[p] += u;
            U[p] = pk2(u, u);
        }

        u64 ta[PPT] = {0ull, 0ull, 0ull, 0ull};
        const float4* Wp = reinterpret_cast<const float4*>(&sW[i * (NJ * NK)]);
        #pragma unroll
        for (int j = 0; j < NJ; ++j) {
            u64 k0[PPT] = {0ull, 0ull, 0ull, 0ull};
            u64 k1[PPT] = {0ull, 0ull, 0ull, 0ull};
            #pragma unroll
            for (int q = 0; q < NK / 4; ++q) {     // 5 x LDS.128, 4 coeffs each
                float4 w4 = Wp[j * (NK / 4) + q];
                u64 wlo = pk2(w4.x, w4.y);         // natural (W_k, W_{k+1}) pairs
                u64 whi = pk2(w4.z, w4.w);
                #pragma unroll
                for (int p = 0; p < PPT; ++p) {
                    k0[p] = fma2(wlo, wv[p][2 * q + 0], k0[p]);
                    k1[p] = fma2(whi, wv[p][2 * q + 1], k1[p]);
                }
            }
            #pragma unroll
            for (int p = 0; p < PPT; ++p)
                ta[p] = fma2(V[p][j], add2(k0[p], k1[p]), ta[p]);
        }
        #pragma unroll
        for (int p = 0; p < PPT; ++p)
            num[p] = fma2(U[p], ta[p], num[p]);
    }

    // merge partner thread's partial numerator and sumu (butterfly over lane^1)
    float nsum[PPT];
    #pragma unroll
    for (int p = 0; p < PPT; ++p) {
        float nlo, nhi;
        upk2(num[p], nlo, nhi);
        nsum[p] = nlo + nhi;
        nsum[p] += __shfl_xor_sync(0xffffffffu, nsum[p], 1);
        sumu[p] += __shfl_xor_sync(0xffffffffu, sumu[p], 1);
    }

    if (half == 0) {
        float4 o;
        o.x = __fdividef(nsum[0], sumu[0] * svw[0]);
        o.y = __fdividef(nsum[1], sumu[1] * svw[1]);
        o.z = __fdividef(nsum[2], sumu[2] * svw[2]);
        o.w = __fdividef(nsum[3], sumu[3] * svw[3]);
        *reinterpret_cast<float4*>(out + p0) = o;
    }
}

extern "C" void kernel_launch(void* const* d_in, const int* in_sizes, int n_in,
                              void* d_out, int out_size) {
    const float* x       = (const float*)d_in[0];
    const float* centers = (const float*)d_in[1];
    const float* beta    = (const float*)d_in[2];
    const float* lin_w   = (const float*)d_in[3];
    float* out = (float*)d_out;

    int N = in_sizes[0] / 3;                    // 131072
    // 2 threads per 4-point group -> TPB/2 groups per block
    int groups = N / PPT;                       // 32768
    int nblocks = (groups * 2 + TPB - 1) / TPB; // 1024

    rbf_sep_kernel<<<nblocks, TPB>>>(x, centers, beta, lin_w, out, N);
}